// round 1
// baseline (speedup 1.0000x reference)
#include <cuda_runtime.h>
#include <cstdint>

#define N_NODES 50000
#define N_EDGES 625000
#define D       128

// Scratch (allocation-free requirement -> __device__ globals)
__device__ float g_agg[N_NODES * D];   // 25.6 MB: partial sums  sum_{e:dst=v} h[src]*(1-d)
__device__ float g_deg[N_NODES];       // in-degree as float
__device__ float g_Wt[D * D];          // W transposed: Wt[k*D + n] = W[n*D + k]

// ---------------------------------------------------------------------------
// Kernel 1: zero scratch + transpose W
// ---------------------------------------------------------------------------
__global__ void zero_prep_kernel(const float* __restrict__ W) {
    int i = blockIdx.x * blockDim.x + threadIdx.x;
    int stride = gridDim.x * blockDim.x;
    float4 z = make_float4(0.f, 0.f, 0.f, 0.f);
    float4* agg4 = reinterpret_cast<float4*>(g_agg);
    const int n4 = N_NODES * D / 4;
    for (int idx = i; idx < n4; idx += stride) agg4[idx] = z;
    for (int idx = i; idx < N_NODES; idx += stride) g_deg[idx] = 0.f;
    // transpose W (coalesced read of W)
    for (int idx = i; idx < D * D; idx += stride) {
        int n = idx / D, k = idx % D;
        g_Wt[k * D + n] = W[idx];
    }
}

// ---------------------------------------------------------------------------
// Kernel 2: edge scatter. One warp per edge.
//   agg[dst] += h[src] * (1 - d);   deg[dst] += 1
// ---------------------------------------------------------------------------
__global__ void __launch_bounds__(256) edge_scatter_kernel(
    const float* __restrict__ h, const float* __restrict__ d,
    const int* __restrict__ src, const int* __restrict__ dst)
{
    int e = blockIdx.x * (blockDim.x >> 5) + (threadIdx.x >> 5);
    if (e >= N_EDGES) return;
    int lane = threadIdx.x & 31;

    int s = __ldg(&src[e]);
    int t = __ldg(&dst[e]);
    float w = 1.0f - __ldg(&d[e]);

    const float4* hs = reinterpret_cast<const float4*>(h + (size_t)s * D);
    float4 v = __ldg(&hs[lane]);
    v.x *= w; v.y *= w; v.z *= w; v.w *= w;

    float* ap = g_agg + (size_t)t * D + lane * 4;
    asm volatile("red.global.add.v4.f32 [%0], {%1,%2,%3,%4};"
                 :: "l"(ap), "f"(v.x), "f"(v.y), "f"(v.z), "f"(v.w)
                 : "memory");
    if (lane == 0) atomicAdd(&g_deg[t], 1.0f);
}

// ---------------------------------------------------------------------------
// Kernel 3: fused gather + GEMM + bias + ReLU
//   x[v] = agg[v] + max(deg[v],1) * h[v]        (== where(deg>0, agg+deg*h, h))
//   out  = relu(x @ W^T + b)
// BM=128 rows, BN=128 cols, BK=8; 256 threads; 8x8 microtile per thread.
// ---------------------------------------------------------------------------
__global__ void __launch_bounds__(256) gemm_relu_kernel(
    const float* __restrict__ h, const float* __restrict__ b,
    float* __restrict__ out)
{
    __shared__ float Xs[128][8];   // [m][k]
    __shared__ float Ws[8][128];   // [k][n]  (from g_Wt)

    const int tid = threadIdx.x;
    const int tx = tid & 15;       // 16 col-threads -> cols tx*8..tx*8+7
    const int ty = tid >> 4;       // 16 row-threads -> rows ty*8..ty*8+7
    const int row0 = blockIdx.x * 128;

    // X-tile load coords: each thread owns one float4 of the 128x8 tile
    const int lr = tid >> 1;            // 0..127
    const int lk = (tid & 1) * 4;       // 0 or 4
    const int grow = row0 + lr;
    const bool rowok = grow < N_NODES;
    const float degv = rowok ? fmaxf(g_deg[grow], 1.0f) : 0.f;
    const float4* hrow = reinterpret_cast<const float4*>(h + (size_t)(rowok ? grow : 0) * D);
    const float4* arow = reinterpret_cast<const float4*>(g_agg + (size_t)(rowok ? grow : 0) * D);

    // W-tile load coords: 8x128 floats, thread loads one float4
    const int wkk = tid >> 5;           // 0..7
    const int wn  = (tid & 31) * 4;     // 0..124

    float acc[8][8];
    #pragma unroll
    for (int i = 0; i < 8; i++)
        #pragma unroll
        for (int j = 0; j < 8; j++) acc[i][j] = 0.f;

    for (int kc = 0; kc < D; kc += 8) {
        // --- load X tile (fused gather) ---
        float4 xv = make_float4(0.f, 0.f, 0.f, 0.f);
        if (rowok) {
            float4 hv = __ldg(&hrow[(kc + lk) >> 2]);
            float4 av = arow[(kc + lk) >> 2];
            xv.x = fmaf(degv, hv.x, av.x);
            xv.y = fmaf(degv, hv.y, av.y);
            xv.z = fmaf(degv, hv.z, av.z);
            xv.w = fmaf(degv, hv.w, av.w);
        }
        *reinterpret_cast<float4*>(&Xs[lr][lk]) = xv;

        // --- load W tile (coalesced from transposed copy) ---
        *reinterpret_cast<float4*>(&Ws[wkk][wn]) =
            *reinterpret_cast<const float4*>(&g_Wt[(kc + wkk) * D + wn]);

        __syncthreads();

        #pragma unroll
        for (int kk = 0; kk < 8; kk++) {
            float a[8], bb[8];
            #pragma unroll
            for (int i = 0; i < 8; i++) a[i] = Xs[ty * 8 + i][kk];
            *reinterpret_cast<float4*>(&bb[0]) = *reinterpret_cast<float4*>(&Ws[kk][tx * 8]);
            *reinterpret_cast<float4*>(&bb[4]) = *reinterpret_cast<float4*>(&Ws[kk][tx * 8 + 4]);
            #pragma unroll
            for (int i = 0; i < 8; i++)
                #pragma unroll
                for (int j = 0; j < 8; j++)
                    acc[i][j] = fmaf(a[i], bb[j], acc[i][j]);
        }
        __syncthreads();
    }

    // --- epilogue: bias + relu + store ---
    float bias[8];
    *reinterpret_cast<float4*>(&bias[0]) = __ldg(reinterpret_cast<const float4*>(&b[tx * 8]));
    *reinterpret_cast<float4*>(&bias[4]) = __ldg(reinterpret_cast<const float4*>(&b[tx * 8 + 4]));

    #pragma unroll
    for (int i = 0; i < 8; i++) {
        int r = row0 + ty * 8 + i;
        if (r >= N_NODES) break;
        float4 o0, o1;
        o0.x = fmaxf(acc[i][0] + bias[0], 0.f);
        o0.y = fmaxf(acc[i][1] + bias[1], 0.f);
        o0.z = fmaxf(acc[i][2] + bias[2], 0.f);
        o0.w = fmaxf(acc[i][3] + bias[3], 0.f);
        o1.x = fmaxf(acc[i][4] + bias[4], 0.f);
        o1.y = fmaxf(acc[i][5] + bias[5], 0.f);
        o1.z = fmaxf(acc[i][6] + bias[6], 0.f);
        o1.w = fmaxf(acc[i][7] + bias[7], 0.f);
        float* orow = out + (size_t)r * D + tx * 8;
        *reinterpret_cast<float4*>(orow)     = o0;
        *reinterpret_cast<float4*>(orow + 4) = o1;
    }
}

// ---------------------------------------------------------------------------
extern "C" void kernel_launch(void* const* d_in, const int* in_sizes, int n_in,
                              void* d_out, int out_size)
{
    const float* h   = (const float*)d_in[0];
    const float* d   = (const float*)d_in[1];
    const int*   src = (const int*)d_in[2];
    const int*   dst = (const int*)d_in[3];
    const float* W   = (const float*)d_in[4];
    const float* b   = (const float*)d_in[5];
    float* out = (float*)d_out;

    // 1) zero scratch + transpose W
    zero_prep_kernel<<<512, 256>>>(W);

    // 2) edge scatter: 1 warp/edge, 8 edges per 256-thread block
    int eblocks = (N_EDGES + 7) / 8;
    edge_scatter_kernel<<<eblocks, 256>>>(h, d, src, dst);

    // 3) fused gather + GEMM + bias + relu
    int gblocks = (N_NODES + 127) / 128;
    gemm_relu_kernel<<<gblocks, 256>>>(h, b, out);
}